// round 1
// baseline (speedup 1.0000x reference)
#include <cuda_runtime.h>

// ---------------- problem constants ----------------
#define BATCH 512
#define NEQv  4096
#define XDIMv 6144
#define H1v   2048
#define H2v   2048
#define YDIMv 4096
#define NEDGE 32768

// ---------------- scratch (device globals; no runtime alloc) ----------------
__device__ __align__(256) float g_z0[BATCH * XDIMv];   // GCN output ++ x_g  [512,6144]
__device__ __align__(256) float g_z1[BATCH * H1v];     // layer1 out         [512,2048]
__device__ __align__(256) float g_z2[BATCH * H2v];     // layer2 out         [512,2048]
__device__ int   g_cnt[NEQv];                          // dst-degree counts
__device__ float g_acc[NEQv];                          // edge scatter accum

// ============================================================
// GCN kernels (tiny)
// ============================================================
__global__ void k_init() {
    int i = blockIdx.x * blockDim.x + threadIdx.x;
    if (i < NEQv) { g_cnt[i] = 0; g_acc[i] = 0.f; }
}

__global__ void k_count(const int* __restrict__ ei) {
    int e = blockIdx.x * blockDim.x + threadIdx.x;
    if (e < NEDGE) atomicAdd(&g_cnt[ei[NEDGE + e]], 1);
}

__global__ void k_scatter(const int* __restrict__ ei, const float* __restrict__ x,
                          const float* __restrict__ gw) {
    int e = blockIdx.x * blockDim.x + threadIdx.x;
    if (e >= NEDGE) return;
    int s = ei[e];            // src node id (< 4096, flattened space)
    int d = ei[NEDGE + e];    // dst node id (< 4096)
    float deg_s = 1.f + 512.f * (float)g_cnt[s];
    // xf[s] = x[s % 512][s / 512]
    float xw = gw[0] * x[(size_t)(s & 511) * XDIMv + (s >> 9)];
    atomicAdd(&g_acc[d], rsqrtf(deg_s) * xw);
}

__global__ void k_build_z(const float* __restrict__ x, const float* __restrict__ gw,
                          const float* __restrict__ gb) {
    int idx = blockIdx.x * blockDim.x + threadIdx.x;
    if (idx >= BATCH * XDIMv) return;
    int b = idx / XDIMv;
    int j = idx - b * XDIMv;
    float v = x[idx];
    float z;
    if (j >= NEQv) {
        z = v;                                   // x_g passthrough, no relu
    } else {
        float w  = gw[0];
        float xw = w * v;
        float out;
        if (j < 8) {                             // only flattened node ids < 4096 touched by edges
            int i = (j << 9) + b;                // i = j*512 + b < 4096
            float deg  = 1.f + 512.f * (float)g_cnt[i];
            out = xw / deg + 512.f * rsqrtf(deg) * g_acc[i] + gb[0];
        } else {
            out = xw + gb[0];                    // deg = 1 (self loop only)
        }
        z = fmaxf(out, 0.f);
    }
    g_z0[idx] = z;
}

// ============================================================
// GEMM: C[M,N] = act(A[M,K] @ W[K,N] + bias)
// split-tf32 (3-MMA) for fp32-grade accuracy on tensor cores
// ============================================================
#define BM 128
#define BN 64
#define BK 32
#define APITCH 36       // conflict-free: bank = (36*r + c) % 32 = lane
#define BPITCH 72       // conflict-free: bank = (8*row + col) % 32
#define STAGES 3
#define STAGE_F (BM * APITCH + BK * BPITCH)      // 6912 floats
#define GEMM_SMEM_BYTES (STAGES * STAGE_F * 4)   // 82944 bytes

__device__ __forceinline__ unsigned smem_u32(const void* p) {
    return (unsigned)__cvta_generic_to_shared(p);
}
__device__ __forceinline__ void cp16(void* dst, const void* src) {
    asm volatile("cp.async.ca.shared.global [%0], [%1], 16;\n"
                 :: "r"(smem_u32(dst)), "l"(src));
}
#define CP_COMMIT() asm volatile("cp.async.commit_group;\n")
#define CP_WAIT1()  asm volatile("cp.async.wait_group 1;\n")

#define MMA_TF32(C, A, B)                                                        \
    asm volatile("mma.sync.aligned.m16n8k8.row.col.f32.tf32.tf32.f32 "           \
                 "{%0,%1,%2,%3},{%4,%5,%6,%7},{%8,%9},{%0,%1,%2,%3};\n"          \
                 : "+f"((C)[0]), "+f"((C)[1]), "+f"((C)[2]), "+f"((C)[3])         \
                 : "r"((A)[0]), "r"((A)[1]), "r"((A)[2]), "r"((A)[3]),            \
                   "r"((B)[0]), "r"((B)[1]))

__device__ __forceinline__ void split_tf32(float v, unsigned& hi, unsigned& lo) {
    hi = __float_as_uint(v) & 0xFFFFE000u;          // RZ-truncated tf32 high part
    float l = v - __uint_as_float(hi);              // exact (Sterbenz)
    lo = __float_as_uint(l);                        // HW reads top 19 bits (RZ) — fine
}

template<int RELU>
__global__ void __launch_bounds__(256, 1) k_gemm(
    const float* __restrict__ A, const float* __restrict__ W,
    const float* __restrict__ bias, float* __restrict__ C,
    int M, int N, int K)
{
    extern __shared__ float smem[];
    const int tid  = threadIdx.x;
    const int lane = tid & 31;
    const int wid  = tid >> 5;
    const int wm   = wid & 3;        // 4 warps in M -> 32 rows each
    const int wn   = wid >> 2;       // 2 warps in N -> 32 cols each
    const int m0   = blockIdx.y * BM;
    const int n0   = blockIdx.x * BN;
    const int r    = lane >> 2;      // group id
    const int q    = lane & 3;       // thread-in-group

    float* As[STAGES]; float* Bs[STAGES];
#pragma unroll
    for (int s = 0; s < STAGES; s++) {
        As[s] = smem + s * STAGE_F;
        Bs[s] = smem + s * STAGE_F + BM * APITCH;
    }

    float c[2][4][4];
#pragma unroll
    for (int i = 0; i < 2; i++)
#pragma unroll
        for (int j = 0; j < 4; j++)
#pragma unroll
            for (int k = 0; k < 4; k++) c[i][j][k] = 0.f;

    const int kIters = K / BK;

    auto loadStage = [&](int it, int stg) {
        const int k0 = it * BK;
        float* as = As[stg];
#pragma unroll
        for (int t = 0; t < 4; t++) {             // A: 128x32 floats = 1024 x 16B
            int ch = tid + t * 256;
            int rr = ch >> 3, c4 = (ch & 7) << 2;
            cp16(&as[rr * APITCH + c4], &A[(size_t)(m0 + rr) * K + k0 + c4]);
        }
        float* bs = Bs[stg];
#pragma unroll
        for (int t = 0; t < 2; t++) {             // W: 32x64 floats = 512 x 16B
            int ch = tid + t * 256;
            int rr = ch >> 4, c4 = (ch & 15) << 2;
            cp16(&bs[rr * BPITCH + c4], &W[(size_t)(k0 + rr) * N + n0 + c4]);
        }
    };

    loadStage(0, 0); CP_COMMIT();
    loadStage(1, 1); CP_COMMIT();

    for (int it = 0; it < kIters; ++it) {
        CP_WAIT1();
        __syncthreads();
        if (it + 2 < kIters) loadStage(it + 2, (it + 2) % STAGES);
        CP_COMMIT();

        const float* as = As[it % STAGES];
        const float* bs = Bs[it % STAGES];

#pragma unroll
        for (int ks = 0; ks < 4; ks++) {
            const int k0 = ks * 8;
            unsigned ah[2][4], al[2][4], bh[4][2], bl[4][2];
#pragma unroll
            for (int mt = 0; mt < 2; mt++) {
                const float* ap = &as[(wm * 32 + mt * 16 + r) * APITCH + k0 + q];
                split_tf32(ap[0],              ah[mt][0], al[mt][0]);
                split_tf32(ap[8 * APITCH],     ah[mt][1], al[mt][1]);
                split_tf32(ap[4],              ah[mt][2], al[mt][2]);
                split_tf32(ap[8 * APITCH + 4], ah[mt][3], al[mt][3]);
            }
#pragma unroll
            for (int nt = 0; nt < 4; nt++) {
                const float* bp = &bs[(k0 + q) * BPITCH + wn * 32 + nt * 8 + r];
                split_tf32(bp[0],          bh[nt][0], bl[nt][0]);
                split_tf32(bp[4 * BPITCH], bh[nt][1], bl[nt][1]);
            }
#pragma unroll
            for (int mt = 0; mt < 2; mt++)
#pragma unroll
                for (int nt = 0; nt < 4; nt++) {
                    MMA_TF32(c[mt][nt], ah[mt], bh[nt]);
                    MMA_TF32(c[mt][nt], ah[mt], bl[nt]);
                    MMA_TF32(c[mt][nt], al[mt], bh[nt]);
                }
        }
    }

    // epilogue: bias + optional relu, float2 stores
#pragma unroll
    for (int mt = 0; mt < 2; mt++) {
#pragma unroll
        for (int nt = 0; nt < 4; nt++) {
            int row0 = m0 + wm * 32 + mt * 16 + r;
            int col0 = n0 + wn * 32 + nt * 8 + 2 * q;
            float bb0 = bias[col0], bb1 = bias[col0 + 1];
            float2 v0 = make_float2(c[mt][nt][0] + bb0, c[mt][nt][1] + bb1);
            float2 v1 = make_float2(c[mt][nt][2] + bb0, c[mt][nt][3] + bb1);
            if (RELU) {
                v0.x = fmaxf(v0.x, 0.f); v0.y = fmaxf(v0.y, 0.f);
                v1.x = fmaxf(v1.x, 0.f); v1.y = fmaxf(v1.y, 0.f);
            }
            *(float2*)&C[(size_t)row0 * N + col0]       = v0;
            *(float2*)&C[(size_t)(row0 + 8) * N + col0] = v1;
        }
    }
}

// ============================================================
// launch
// ============================================================
extern "C" void kernel_launch(void* const* d_in, const int* in_sizes, int n_in,
                              void* d_out, int out_size) {
    const float* x  = (const float*)d_in[0];
    const int*   ei = (const int*)  d_in[1];
    const float* gw = (const float*)d_in[2];
    const float* gb = (const float*)d_in[3];
    const float* W1 = (const float*)d_in[4];
    const float* b1 = (const float*)d_in[5];
    const float* W2 = (const float*)d_in[6];
    const float* b2 = (const float*)d_in[7];
    const float* W3 = (const float*)d_in[8];
    const float* b3 = (const float*)d_in[9];
    float* out = (float*)d_out;

    cudaFuncSetAttribute(k_gemm<1>, cudaFuncAttributeMaxDynamicSharedMemorySize, GEMM_SMEM_BYTES);
    cudaFuncSetAttribute(k_gemm<0>, cudaFuncAttributeMaxDynamicSharedMemorySize, GEMM_SMEM_BYTES);

    void *z0p, *z1p, *z2p;
    cudaGetSymbolAddress(&z0p, g_z0);
    cudaGetSymbolAddress(&z1p, g_z1);
    cudaGetSymbolAddress(&z2p, g_z2);
    float* z0 = (float*)z0p;
    float* z1 = (float*)z1p;
    float* z2 = (float*)z2p;

    // GCN
    k_init<<<NEQv / 256, 256>>>();
    k_count<<<NEDGE / 256, 256>>>(ei);
    k_scatter<<<NEDGE / 256, 256>>>(ei, x, gw);
    k_build_z<<<(BATCH * XDIMv) / 256, 256>>>(x, gw, gb);

    // MLP: z1 = relu(z0@W1+b1); z2 = relu(z1@W2+b2); out = z2@W3+b3
    dim3 g1(H1v / BN,   BATCH / BM);   // (32, 4)
    dim3 g2(H2v / BN,   BATCH / BM);   // (32, 4)
    dim3 g3(YDIMv / BN, BATCH / BM);   // (64, 4)
    k_gemm<1><<<g1, 256, GEMM_SMEM_BYTES>>>(z0, W1, b1, z1, BATCH, H1v,   XDIMv);
    k_gemm<1><<<g2, 256, GEMM_SMEM_BYTES>>>(z1, W2, b2, z2, BATCH, H2v,   H1v);
    k_gemm<0><<<g3, 256, GEMM_SMEM_BYTES>>>(z2, W3, b3, out, BATCH, YDIMv, H2v);
}